// round 1
// baseline (speedup 1.0000x reference)
#include <cuda_runtime.h>
#include <math.h>

// ---------------------------------------------------------------------------
// DiffAttention  B=1 S=2048 HID=2048 H=16 KVH=8 HD=128
// ---------------------------------------------------------------------------
namespace {
constexpr int S_LEN   = 2048;
constexpr int HID_DIM = 2048;
constexpr int NH      = 16;
constexpr int NKV     = 8;
constexpr int DH      = 128;
constexpr float ATT_SCALE = 0.08838834764831845f;   // 128^-0.5
constexpr float LAM0      = 0.2f;
constexpr float EPSV      = 1e-5f;
constexpr long long ATTN_ELEMS = (long long)NH * S_LEN * S_LEN;   // 67108864
constexpr long long OUT_ELEMS  = (long long)S_LEN * (NH * DH);    // 4194304
}

// scratch (device globals: allocation-free contract)
__device__ float g_Q [S_LEN * NH  * DH];
__device__ float g_K [S_LEN * NKV * DH];
__device__ float g_QN[S_LEN * NH  * DH];
__device__ float g_KN[S_LEN * NKV * DH];
__device__ float g_V [S_LEN * NKV * 2 * DH];
__device__ float g_aw[(long long)NH * S_LEN * S_LEN];
__device__ float g_an[(long long)NH * S_LEN * S_LEN];
__device__ float g_o [NH * S_LEN * 2 * DH];
__device__ float g_y [S_LEN * NH * 2 * DH];
__device__ float g_lam[NH];
__device__ float g_mu[2 * NH];
__device__ float g_rstd[2 * NH];

// ---------------------------------------------------------------------------
// SGEMM NT:  C[m,n] = alpha * sum_k A[m,k]*B[n,k] + bias[n]
// A: [M,K] k-contig (lda), B: [N,K] k-contig (ldb).
// Batched over blockIdx.z:  A += z*sA,  B += (z>>zshB)*sB,  C += z*sC.
// Tiles 128x128x8, 256 threads, 8x8 per thread. All dims assumed divisible.
// ---------------------------------------------------------------------------
__global__ void __launch_bounds__(256) sgemm_nt(
    const float* __restrict__ A, const float* __restrict__ B,
    const float* __restrict__ bias, float* __restrict__ C,
    int K, int lda, int ldb, int ldc,
    long long sA, long long sB, int zshB, long long sC, float alpha)
{
    __shared__ float As[8][128];
    __shared__ float Bs[8][128];
    const int z = blockIdx.z;
    A += (long long)z * sA;
    B += (long long)(z >> zshB) * sB;
    C += (long long)z * sC;
    const int m0 = blockIdx.y << 7, n0 = blockIdx.x << 7;
    const int tid = threadIdx.x;
    const int tx = tid & 15, ty = tid >> 4;
    const int lrow = tid >> 1, lk = (tid & 1) << 2;
    const float* Ap = A + (long long)(m0 + lrow) * lda + lk;
    const float* Bp = B + (long long)(n0 + lrow) * ldb + lk;
    float acc[8][8];
#pragma unroll
    for (int i = 0; i < 8; ++i)
#pragma unroll
        for (int j = 0; j < 8; ++j) acc[i][j] = 0.f;

    for (int k0 = 0; k0 < K; k0 += 8) {
        float4 a4 = *(const float4*)Ap; Ap += 8;
        float4 b4 = *(const float4*)Bp; Bp += 8;
        As[lk+0][lrow] = a4.x; As[lk+1][lrow] = a4.y;
        As[lk+2][lrow] = a4.z; As[lk+3][lrow] = a4.w;
        Bs[lk+0][lrow] = b4.x; Bs[lk+1][lrow] = b4.y;
        Bs[lk+2][lrow] = b4.z; Bs[lk+3][lrow] = b4.w;
        __syncthreads();
#pragma unroll
        for (int kk = 0; kk < 8; ++kk) {
            float ra[8], rb[8];
            *(float4*)(ra)     = *(const float4*)&As[kk][ty << 3];
            *(float4*)(ra + 4) = *(const float4*)&As[kk][(ty << 3) + 4];
            *(float4*)(rb)     = *(const float4*)&Bs[kk][tx << 3];
            *(float4*)(rb + 4) = *(const float4*)&Bs[kk][(tx << 3) + 4];
#pragma unroll
            for (int i = 0; i < 8; ++i)
#pragma unroll
                for (int j = 0; j < 8; ++j)
                    acc[i][j] += ra[i] * rb[j];
        }
        __syncthreads();
    }

    float bb[8];
    if (bias) {
        *(float4*)bb       = *(const float4*)&bias[n0 + (tx << 3)];
        *(float4*)(bb + 4) = *(const float4*)&bias[n0 + (tx << 3) + 4];
    } else {
#pragma unroll
        for (int j = 0; j < 8; ++j) bb[j] = 0.f;
    }
#pragma unroll
    for (int i = 0; i < 8; ++i) {
        float* Cp = C + (long long)(m0 + (ty << 3) + i) * ldc + n0 + (tx << 3);
        float4 o0, o1;
        o0.x = acc[i][0]*alpha + bb[0]; o0.y = acc[i][1]*alpha + bb[1];
        o0.z = acc[i][2]*alpha + bb[2]; o0.w = acc[i][3]*alpha + bb[3];
        o1.x = acc[i][4]*alpha + bb[4]; o1.y = acc[i][5]*alpha + bb[5];
        o1.z = acc[i][6]*alpha + bb[6]; o1.w = acc[i][7]*alpha + bb[7];
        *(float4*)Cp       = o0;
        *(float4*)(Cp + 4) = o1;
    }
}

// ---------------------------------------------------------------------------
// SGEMM NN:  C[m,n] = sum_k A[m,k]*B[k,n]
// A: [M,K] k-contig (lda), B: [K,N] n-contig (ldb).
// ---------------------------------------------------------------------------
__global__ void __launch_bounds__(256) sgemm_nn(
    const float* __restrict__ A, const float* __restrict__ B,
    float* __restrict__ C,
    int K, int lda, int ldb, int ldc,
    long long sA, long long sB, int zshB, long long sC)
{
    __shared__ float As[8][128];
    __shared__ float Bs[8][128];
    const int z = blockIdx.z;
    A += (long long)z * sA;
    B += (long long)(z >> zshB) * sB;
    C += (long long)z * sC;
    const int m0 = blockIdx.y << 7, n0 = blockIdx.x << 7;
    const int tid = threadIdx.x;
    const int tx = tid & 15, ty = tid >> 4;
    const int lrow = tid >> 1, lk = (tid & 1) << 2;
    const int brow = tid >> 5, bcol = (tid & 31) << 2;
    const float* Ap = A + (long long)(m0 + lrow) * lda + lk;
    const float* Bp = B + (long long)brow * ldb + n0 + bcol;
    float acc[8][8];
#pragma unroll
    for (int i = 0; i < 8; ++i)
#pragma unroll
        for (int j = 0; j < 8; ++j) acc[i][j] = 0.f;

    for (int k0 = 0; k0 < K; k0 += 8) {
        float4 a4 = *(const float4*)Ap; Ap += 8;
        float4 b4 = *(const float4*)Bp; Bp += (long long)8 * ldb;
        As[lk+0][lrow] = a4.x; As[lk+1][lrow] = a4.y;
        As[lk+2][lrow] = a4.z; As[lk+3][lrow] = a4.w;
        *(float4*)&Bs[brow][bcol] = b4;
        __syncthreads();
#pragma unroll
        for (int kk = 0; kk < 8; ++kk) {
            float ra[8], rb[8];
            *(float4*)(ra)     = *(const float4*)&As[kk][ty << 3];
            *(float4*)(ra + 4) = *(const float4*)&As[kk][(ty << 3) + 4];
            *(float4*)(rb)     = *(const float4*)&Bs[kk][tx << 3];
            *(float4*)(rb + 4) = *(const float4*)&Bs[kk][(tx << 3) + 4];
#pragma unroll
            for (int i = 0; i < 8; ++i)
#pragma unroll
                for (int j = 0; j < 8; ++j)
                    acc[i][j] += ra[i] * rb[j];
        }
        __syncthreads();
    }
#pragma unroll
    for (int i = 0; i < 8; ++i) {
        float* Cp = C + (long long)(m0 + (ty << 3) + i) * ldc + n0 + (tx << 3);
        *(float4*)Cp       = *(float4*)&acc[i][0];
        *(float4*)(Cp + 4) = *(float4*)&acc[i][4];
    }
}

// ---------------------------------------------------------------------------
// RoPE in place on [S, HH, 128]; pair (d, d+64)
// x'[d]    = x[d]*cos[d]    - x[d+64]*sin[d]
// x'[d+64] = x[d+64]*cos[d+64] + x[d]*sin[d+64]
// ---------------------------------------------------------------------------
__global__ void rope_kernel(float* __restrict__ Xv,
                            const float* __restrict__ cs,
                            const float* __restrict__ sn, int HH)
{
    int idx = blockIdx.x * 256 + threadIdx.x;
    int total = S_LEN * HH * 64;
    if (idx >= total) return;
    int d = idx & 63;
    int h = (idx >> 6) % HH;
    int s = idx / (HH * 64);
    float c0 = cs[s * DH + d],       s0 = sn[s * DH + d];
    float c1 = cs[s * DH + 64 + d],  s1 = sn[s * DH + 64 + d];
    long long base = ((long long)s * HH + h) * DH;
    float x0 = Xv[base + d], x1 = Xv[base + 64 + d];
    Xv[base + d]      = x0 * c0 - x1 * s0;
    Xv[base + 64 + d] = x1 * c1 + x0 * s1;
}

// lam[h] = exp(dot(lq1,lk1)) - exp(dot(lq2,lk2)) + 0.2
__global__ void lam_kernel(const float* __restrict__ lq1, const float* __restrict__ lk1,
                           const float* __restrict__ lq2, const float* __restrict__ lk2)
{
    int h = blockIdx.x, t = threadIdx.x;
    float a = lq1[h * DH + t] * lk1[h * DH + t];
    float b = lq2[h * DH + t] * lk2[h * DH + t];
#pragma unroll
    for (int o = 16; o; o >>= 1) {
        a += __shfl_xor_sync(0xffffffffu, a, o);
        b += __shfl_xor_sync(0xffffffffu, b, o);
    }
    __shared__ float sa[4], sb[4];
    if ((t & 31) == 0) { sa[t >> 5] = a; sb[t >> 5] = b; }
    __syncthreads();
    if (t == 0) {
        float A = sa[0] + sa[1] + sa[2] + sa[3];
        float B = sb[0] + sb[1] + sb[2] + sb[3];
        g_lam[h] = expf(A) - expf(B) + LAM0;
    }
}

// attn = softmax(aw) - lam[h]*softmax(an); one block per (h,q) row.
__global__ void __launch_bounds__(256) softmax_combine(
    const float* __restrict__ aw, const float* __restrict__ an,
    float* __restrict__ attn)
{
    const int q = blockIdx.x, h = blockIdx.y;
    const long long off = ((long long)h * S_LEN + q) * S_LEN;
    const float* r1 = aw + off;
    const float* r2 = an + off;
    const int t = threadIdx.x;
    float v1[8], v2[8];
    float m1 = -1e30f, m2 = -1e30f;
#pragma unroll
    for (int i = 0; i < 8; ++i) {
        v1[i] = r1[t + (i << 8)];
        v2[i] = r2[t + (i << 8)];
        m1 = fmaxf(m1, v1[i]);
        m2 = fmaxf(m2, v2[i]);
    }
    __shared__ float sm1[8], sm2[8];
#pragma unroll
    for (int o = 16; o; o >>= 1) {
        m1 = fmaxf(m1, __shfl_xor_sync(0xffffffffu, m1, o));
        m2 = fmaxf(m2, __shfl_xor_sync(0xffffffffu, m2, o));
    }
    if ((t & 31) == 0) { sm1[t >> 5] = m1; sm2[t >> 5] = m2; }
    __syncthreads();
    m1 = sm1[0]; m2 = sm2[0];
#pragma unroll
    for (int i = 1; i < 8; ++i) { m1 = fmaxf(m1, sm1[i]); m2 = fmaxf(m2, sm2[i]); }
    float s1 = 0.f, s2 = 0.f;
#pragma unroll
    for (int i = 0; i < 8; ++i) {
        v1[i] = expf(v1[i] - m1); s1 += v1[i];
        v2[i] = expf(v2[i] - m2); s2 += v2[i];
    }
#pragma unroll
    for (int o = 16; o; o >>= 1) {
        s1 += __shfl_xor_sync(0xffffffffu, s1, o);
        s2 += __shfl_xor_sync(0xffffffffu, s2, o);
    }
    __syncthreads();                 // protect sm reuse
    if ((t & 31) == 0) { sm1[t >> 5] = s1; sm2[t >> 5] = s2; }
    __syncthreads();
    s1 = 0.f; s2 = 0.f;
#pragma unroll
    for (int i = 0; i < 8; ++i) { s1 += sm1[i]; s2 += sm2[i]; }
    const float i1 = 1.f / s1;
    const float i2 = g_lam[h] / s2;
    float* w = attn + off;
#pragma unroll
    for (int i = 0; i < 8; ++i)
        w[t + (i << 8)] = v1[i] * i1 - v2[i] * i2;
}

// group g = h*2 + (q>=1024): contiguous 262144-float block of g_o
__global__ void group_stats_kernel(const float* __restrict__ ob)
{
    const int g = blockIdx.x;
    const float4* p = (const float4*)(ob + (long long)g * 262144);
    float s = 0.f, ss = 0.f;
    for (int i = threadIdx.x; i < 65536; i += 1024) {
        float4 v = p[i];
        s  += v.x + v.y + v.z + v.w;
        ss += v.x * v.x + v.y * v.y + v.z * v.z + v.w * v.w;
    }
    __shared__ float sa[32], sb[32];
    int t = threadIdx.x;
#pragma unroll
    for (int o = 16; o; o >>= 1) {
        s  += __shfl_xor_sync(0xffffffffu, s, o);
        ss += __shfl_xor_sync(0xffffffffu, ss, o);
    }
    if ((t & 31) == 0) { sa[t >> 5] = s; sb[t >> 5] = ss; }
    __syncthreads();
    if (t < 32) {
        s = sa[t]; ss = sb[t];
#pragma unroll
        for (int o = 16; o; o >>= 1) {
            s  += __shfl_xor_sync(0xffffffffu, s, o);
            ss += __shfl_xor_sync(0xffffffffu, ss, o);
        }
        if (t == 0) {
            float mu  = s * (1.f / 262144.f);
            float var = ss * (1.f / 262144.f) - mu * mu;
            g_mu[g]   = mu;
            g_rstd[g] = rsqrtf(var + EPSV);
        }
    }
}

// y_flat[q, h*256+d] = ((o[h,q,d]-mu)*rstd*gamma[r]+beta[r]) * 0.8,  r=(q%1024)>>3
__global__ void apply_norm_kernel(const float* __restrict__ ob,
                                  const float* __restrict__ gamma,
                                  const float* __restrict__ beta,
                                  float* __restrict__ y)
{
    int idx = blockIdx.x * 256 + threadIdx.x;      // over 16*2048*256 = 8388608
    int d = idx & 255;
    int q = (idx >> 8) & 2047;
    int h = idx >> 19;
    int g = (h << 1) + (q >> 10);
    int r = (q & 1023) >> 3;
    float v = (ob[idx] - g_mu[g]) * g_rstd[g] * gamma[r] + beta[r];
    y[((long long)q << 12) + (h << 8) + d] = v * 0.8f;   // *(1-LAMBDA_INIT)
}

// ---------------------------------------------------------------------------
extern "C" void kernel_launch(void* const* d_in, const int* in_sizes, int n_in,
                              void* d_out, int out_size)
{
    const float* X    = (const float*)d_in[0];
    const float* cs   = (const float*)d_in[1];
    const float* sn   = (const float*)d_in[2];
    const float* Wq   = (const float*)d_in[3];
    const float* bq   = (const float*)d_in[4];
    const float* Wk   = (const float*)d_in[5];
    const float* bk   = (const float*)d_in[6];
    const float* Wqn  = (const float*)d_in[7];
    const float* bqn  = (const float*)d_in[8];
    const float* Wkn  = (const float*)d_in[9];
    const float* bkn  = (const float*)d_in[10];
    const float* Wv   = (const float*)d_in[11];
    const float* bv   = (const float*)d_in[12];
    const float* Wo   = (const float*)d_in[13];
    const float* bo   = (const float*)d_in[14];
    const float* lq1  = (const float*)d_in[15];
    const float* lk1  = (const float*)d_in[16];
    const float* lq2  = (const float*)d_in[17];
    const float* lk2  = (const float*)d_in[18];
    const float* gam  = (const float*)d_in[19];
    const float* bet  = (const float*)d_in[20];

    float *pQ, *pK, *pQN, *pKN, *pV, *paw, *pan, *po, *py;
    cudaGetSymbolAddress((void**)&pQ,  g_Q);
    cudaGetSymbolAddress((void**)&pK,  g_K);
    cudaGetSymbolAddress((void**)&pQN, g_QN);
    cudaGetSymbolAddress((void**)&pKN, g_KN);
    cudaGetSymbolAddress((void**)&pV,  g_V);
    cudaGetSymbolAddress((void**)&paw, g_aw);
    cudaGetSymbolAddress((void**)&pan, g_an);
    cudaGetSymbolAddress((void**)&po,  g_o);
    cudaGetSymbolAddress((void**)&py,  g_y);

    float* outp  = (float*)d_out;
    // reference returns (output, attn): write attn after output if room,
    // else keep it in scratch (in-place over aw).
    float* attnp = ((long long)out_size >= OUT_ELEMS + ATTN_ELEMS)
                       ? (outp + OUT_ELEMS) : paw;

    // 1. projections: C = X @ W^T + b
    sgemm_nt<<<dim3(16,16,1), 256>>>(X, Wq,  bq,  pQ,  2048, 2048, 2048, 2048, 0,0,0,0, 1.f);
    sgemm_nt<<<dim3( 8,16,1), 256>>>(X, Wk,  bk,  pK,  2048, 2048, 2048, 1024, 0,0,0,0, 1.f);
    sgemm_nt<<<dim3(16,16,1), 256>>>(X, Wqn, bqn, pQN, 2048, 2048, 2048, 2048, 0,0,0,0, 1.f);
    sgemm_nt<<<dim3( 8,16,1), 256>>>(X, Wkn, bkn, pKN, 2048, 2048, 2048, 1024, 0,0,0,0, 1.f);
    sgemm_nt<<<dim3(16,16,1), 256>>>(X, Wv,  bv,  pV,  2048, 2048, 2048, 2048, 0,0,0,0, 1.f);

    // 2. RoPE
    rope_kernel<<<(S_LEN*16*64)/256, 256>>>(pQ,  cs, sn, 16);
    rope_kernel<<<(S_LEN* 8*64)/256, 256>>>(pK,  cs, sn,  8);
    rope_kernel<<<(S_LEN*16*64)/256, 256>>>(pQN, cs, sn, 16);
    rope_kernel<<<(S_LEN* 8*64)/256, 256>>>(pKN, cs, sn,  8);

    // 3. lambda
    lam_kernel<<<16, 128>>>(lq1, lk1, lq2, lk2);

    // 4. scores: aw/an = scale * Q K^T (GQA: kv head = h>>1 via zshB=1)
    sgemm_nt<<<dim3(16,16,16), 256>>>(pQ,  pK,  nullptr, paw, 128, 2048, 1024, 2048,
                                      128, 128, 1, (long long)S_LEN*S_LEN, ATT_SCALE);
    sgemm_nt<<<dim3(16,16,16), 256>>>(pQN, pKN, nullptr, pan, 128, 2048, 1024, 2048,
                                      128, 128, 1, (long long)S_LEN*S_LEN, ATT_SCALE);

    // 5. attn = softmax(aw) - lam*softmax(an)
    softmax_combine<<<dim3(S_LEN, NH), 256>>>(paw, pan, attnp);

    // 6. out = attn @ V   (V sub-block per kv head: offset (h>>1)*256)
    sgemm_nn<<<dim3(2,16,16), 256>>>(attnp, pV, po, 2048, 2048, 2048, 256,
                                     (long long)S_LEN*S_LEN, 256, 1,
                                     (long long)S_LEN*256);

    // 7. group stats + normalize/scatter into y_flat [2048, 4096]
    group_stats_kernel<<<32, 1024>>>(po);
    apply_norm_kernel<<<(16*2048*256)/256, 256>>>(po, gam, bet, py);

    // 8. output = y @ Wo^T + bo
    sgemm_nt<<<dim3(16,16,1), 256>>>(py, Wo, bo, outp, 4096, 4096, 4096, 2048,
                                     0,0,0,0, 1.f);
}

// round 2
// speedup vs baseline: 2.7724x; 2.7724x over previous
#include <cuda_runtime.h>
#include <math.h>
#include <stdint.h>

// ---------------------------------------------------------------------------
// DiffAttention  B=1 S=2048 HID=2048 H=16 KVH=8 HD=128  — tf32 tensor-core build
// ---------------------------------------------------------------------------
namespace {
constexpr int S_LEN   = 2048;
constexpr int NH      = 16;
constexpr int NKV     = 8;
constexpr int DH      = 128;
constexpr float ATT_SCALE = 0.08838834764831845f;   // 128^-0.5
constexpr float LAM0      = 0.2f;
constexpr float EPSV      = 1e-5f;
constexpr long long ATTN_ELEMS = (long long)NH * S_LEN * S_LEN;   // 67108864
constexpr long long OUT_ELEMS  = (long long)S_LEN * (NH * DH);    // 4194304
}

// scratch (device globals: allocation-free contract)
__device__ float g_Q [S_LEN * NH  * DH];
__device__ float g_K [S_LEN * NKV * DH];
__device__ float g_QN[S_LEN * NH  * DH];
__device__ float g_KN[S_LEN * NKV * DH];
__device__ float g_V [S_LEN * NKV * 2 * DH];
__device__ float g_Vt[S_LEN * NKV * 2 * DH];     // V transposed: [2048 cols][2048 seq]
__device__ float g_aw[(long long)NH * S_LEN * S_LEN];
__device__ float g_an[(long long)NH * S_LEN * S_LEN];
__device__ float g_o [NH * S_LEN * 2 * DH];
__device__ float g_y [S_LEN * NH * 2 * DH];
__device__ float g_lam[NH];
__device__ float g_mu[2 * NH];
__device__ float g_rstd[2 * NH];

// ---------------------------------------------------------------------------
// tf32 helpers
// ---------------------------------------------------------------------------
__device__ __forceinline__ float to_tf32(float x) {
    uint32_t r;
    asm("cvt.rna.tf32.f32 %0, %1;" : "=r"(r) : "f"(x));
    return __uint_as_float(r);
}
__device__ __forceinline__ float4 f4_tf32(float4 v) {
    v.x = to_tf32(v.x); v.y = to_tf32(v.y);
    v.z = to_tf32(v.z); v.w = to_tf32(v.w);
    return v;
}
__device__ __forceinline__ void mma_tf32(float* c, const uint32_t* a, const uint32_t* b) {
    asm volatile(
        "mma.sync.aligned.m16n8k8.row.col.f32.tf32.tf32.f32 "
        "{%0,%1,%2,%3}, {%4,%5,%6,%7}, {%8,%9}, {%0,%1,%2,%3};\n"
        : "+f"(c[0]), "+f"(c[1]), "+f"(c[2]), "+f"(c[3])
        : "r"(a[0]), "r"(a[1]), "r"(a[2]), "r"(a[3]),
          "r"(b[0]), "r"(b[1]));
}

// ---------------------------------------------------------------------------
// Tensor-core GEMM NT:  C[m,n] = alpha * sum_k A[m,k]*B[n,k] + bias[n]
// A: [M,K] k-contig (lda), B: [N,K] k-contig (ldb).
// Batched over blockIdx.z:  A += z*sA,  B += (z>>zshB)*sB,  C += z*sC.
// Block tile 128x128, BK=16, 8 warps (2x4), warp tile 64x32 (4x4 m16n8k8).
// Double-buffered smem, register-staged global prefetch, tf32 rna conversion.
// M, N multiples of 128; K multiple of 16.
// ---------------------------------------------------------------------------
__global__ void __launch_bounds__(256, 2) tgemm_nt(
    const float* __restrict__ A, const float* __restrict__ B,
    const float* __restrict__ bias, float* __restrict__ C,
    int K, int lda, int ldb, int ldc,
    long long sA, long long sB, int zshB, long long sC, float alpha)
{
    __shared__ float As[2][128][20];   // pitch 20 -> conflict-free frag loads
    __shared__ float Bs[2][128][20];

    const int z = blockIdx.z;
    A += (long long)z * sA;
    B += (long long)(z >> zshB) * sB;
    C += (long long)z * sC;
    const int m0 = blockIdx.y << 7, n0 = blockIdx.x << 7;
    const int tid  = threadIdx.x;
    const int wid  = tid >> 5, lane = tid & 31;
    const int wm   = (wid & 1) << 6;        // warp m offset: 0 / 64
    const int wn   = (wid >> 1) << 5;       // warp n offset: 0..96
    const int gid  = lane >> 2, tig = lane & 3;

    // staging: each thread moves 2 float4 of A and 2 of B per 128x16 tile
    const int srow = tid >> 2;              // 0..63
    const int scol = (tid & 3) << 2;        // 0,4,8,12
    const float* Ag = A + (long long)(m0 + srow) * lda + scol;
    const float* Bg = B + (long long)(n0 + srow) * ldb + scol;
    const long long ldA64 = (long long)64 * lda;
    const long long ldB64 = (long long)64 * ldb;

    float acc[4][4][4];
#pragma unroll
    for (int i = 0; i < 4; ++i)
#pragma unroll
        for (int j = 0; j < 4; ++j)
#pragma unroll
            for (int v = 0; v < 4; ++v) acc[i][j][v] = 0.f;

    // prologue: stage tile 0
    float4 ra0 = *(const float4*)Ag;
    float4 ra1 = *(const float4*)(Ag + ldA64);
    float4 rb0 = *(const float4*)Bg;
    float4 rb1 = *(const float4*)(Bg + ldB64);
    *(float4*)&As[0][srow     ][scol] = f4_tf32(ra0);
    *(float4*)&As[0][srow + 64][scol] = f4_tf32(ra1);
    *(float4*)&Bs[0][srow     ][scol] = f4_tf32(rb0);
    *(float4*)&Bs[0][srow + 64][scol] = f4_tf32(rb1);
    __syncthreads();

    const int T = K >> 4;
    for (int t = 0; t < T; ++t) {
        if (t + 1 < T) {                    // prefetch next tile into registers
            const float* Ap = Ag + ((t + 1) << 4);
            const float* Bp = Bg + ((t + 1) << 4);
            ra0 = *(const float4*)Ap;  ra1 = *(const float4*)(Ap + ldA64);
            rb0 = *(const float4*)Bp;  rb1 = *(const float4*)(Bp + ldB64);
        }
        const int buf = t & 1;
        const float (*Ab)[20] = As[buf];
        const float (*Bb)[20] = Bs[buf];
#pragma unroll
        for (int kk = 0; kk < 16; kk += 8) {
            uint32_t a[4][4], b[4][2];
#pragma unroll
            for (int mt = 0; mt < 4; ++mt) {
                const int r = wm + (mt << 4) + gid;
                a[mt][0] = __float_as_uint(Ab[r    ][kk + tig]);
                a[mt][1] = __float_as_uint(Ab[r + 8][kk + tig]);
                a[mt][2] = __float_as_uint(Ab[r    ][kk + tig + 4]);
                a[mt][3] = __float_as_uint(Ab[r + 8][kk + tig + 4]);
            }
#pragma unroll
            for (int nt = 0; nt < 4; ++nt) {
                const int c = wn + (nt << 3) + gid;
                b[nt][0] = __float_as_uint(Bb[c][kk + tig]);
                b[nt][1] = __float_as_uint(Bb[c][kk + tig + 4]);
            }
#pragma unroll
            for (int mt = 0; mt < 4; ++mt)
#pragma unroll
                for (int nt = 0; nt < 4; ++nt)
                    mma_tf32(acc[mt][nt], a[mt], b[nt]);
        }
        if (t + 1 < T) {
            __syncthreads();                // everyone done reading buf^1
            const int nb = buf ^ 1;
            *(float4*)&As[nb][srow     ][scol] = f4_tf32(ra0);
            *(float4*)&As[nb][srow + 64][scol] = f4_tf32(ra1);
            *(float4*)&Bs[nb][srow     ][scol] = f4_tf32(rb0);
            *(float4*)&Bs[nb][srow + 64][scol] = f4_tf32(rb1);
            __syncthreads();
        }
    }

    // epilogue: alpha * acc + bias, float2 stores
#pragma unroll
    for (int nt = 0; nt < 4; ++nt) {
        const int c0 = n0 + wn + (nt << 3) + (tig << 1);
        const float b0 = bias ? bias[c0]     : 0.f;
        const float b1 = bias ? bias[c0 + 1] : 0.f;
#pragma unroll
        for (int mt = 0; mt < 4; ++mt) {
            const int r = m0 + wm + (mt << 4) + gid;
            float2 v;
            v.x = acc[mt][nt][0] * alpha + b0;
            v.y = acc[mt][nt][1] * alpha + b1;
            *(float2*)&C[(long long)r * ldc + c0] = v;
            v.x = acc[mt][nt][2] * alpha + b0;
            v.y = acc[mt][nt][3] * alpha + b1;
            *(float2*)&C[(long long)(r + 8) * ldc + c0] = v;
        }
    }
}

// ---------------------------------------------------------------------------
// 2048x2048 transpose (for V -> Vt so PV GEMM is NT)
// ---------------------------------------------------------------------------
__global__ void transpose2048(const float* __restrict__ in, float* __restrict__ out)
{
    __shared__ float tile[32][33];
    int x = blockIdx.x * 32 + threadIdx.x;
    int y = blockIdx.y * 32 + threadIdx.y;
#pragma unroll
    for (int i = 0; i < 32; i += 8)
        tile[threadIdx.y + i][threadIdx.x] = in[(long long)(y + i) * 2048 + x];
    __syncthreads();
    x = blockIdx.y * 32 + threadIdx.x;
    y = blockIdx.x * 32 + threadIdx.y;
#pragma unroll
    for (int i = 0; i < 32; i += 8)
        out[(long long)(y + i) * 2048 + x] = tile[threadIdx.x][threadIdx.y + i];
}

// ---------------------------------------------------------------------------
// RoPE in place on [S, HH, 128]; pair (d, d+64)
// ---------------------------------------------------------------------------
__global__ void rope_kernel(float* __restrict__ Xv,
                            const float* __restrict__ cs,
                            const float* __restrict__ sn, int HH)
{
    int idx = blockIdx.x * 256 + threadIdx.x;
    int total = S_LEN * HH * 64;
    if (idx >= total) return;
    int d = idx & 63;
    int h = (idx >> 6) % HH;
    int s = idx / (HH * 64);
    float c0 = cs[s * DH + d],       s0 = sn[s * DH + d];
    float c1 = cs[s * DH + 64 + d],  s1 = sn[s * DH + 64 + d];
    long long base = ((long long)s * HH + h) * DH;
    float x0 = Xv[base + d], x1 = Xv[base + 64 + d];
    Xv[base + d]      = x0 * c0 - x1 * s0;
    Xv[base + 64 + d] = x1 * c1 + x0 * s1;
}

// lam[h] = exp(dot(lq1,lk1)) - exp(dot(lq2,lk2)) + 0.2
__global__ void lam_kernel(const float* __restrict__ lq1, const float* __restrict__ lk1,
                           const float* __restrict__ lq2, const float* __restrict__ lk2)
{
    int h = blockIdx.x, t = threadIdx.x;
    float a = lq1[h * DH + t] * lk1[h * DH + t];
    float b = lq2[h * DH + t] * lk2[h * DH + t];
#pragma unroll
    for (int o = 16; o; o >>= 1) {
        a += __shfl_xor_sync(0xffffffffu, a, o);
        b += __shfl_xor_sync(0xffffffffu, b, o);
    }
    __shared__ float sa[4], sb[4];
    if ((t & 31) == 0) { sa[t >> 5] = a; sb[t >> 5] = b; }
    __syncthreads();
    if (t == 0) {
        float A = sa[0] + sa[1] + sa[2] + sa[3];
        float B = sb[0] + sb[1] + sb[2] + sb[3];
        g_lam[h] = expf(A) - expf(B) + LAM0;
    }
}

// attn = softmax(aw) - lam[h]*softmax(an); one block per (h,q) row.
__global__ void __launch_bounds__(256) softmax_combine(
    const float* __restrict__ aw, const float* __restrict__ an,
    float* __restrict__ attn)
{
    const int q = blockIdx.x, h = blockIdx.y;
    const long long off = ((long long)h * S_LEN + q) * S_LEN;
    const float* r1 = aw + off;
    const float* r2 = an + off;
    const int t = threadIdx.x;
    float v1[8], v2[8];
    float m1 = -1e30f, m2 = -1e30f;
#pragma unroll
    for (int i = 0; i < 8; ++i) {
        v1[i] = r1[t + (i << 8)];
        v2[i] = r2[t + (i << 8)];
        m1 = fmaxf(m1, v1[i]);
        m2 = fmaxf(m2, v2[i]);
    }
    __shared__ float sm1[8], sm2[8];
#pragma unroll
    for (int o = 16; o; o >>= 1) {
        m1 = fmaxf(m1, __shfl_xor_sync(0xffffffffu, m1, o));
        m2 = fmaxf(m2, __shfl_xor_sync(0xffffffffu, m2, o));
    }
    if ((t & 31) == 0) { sm1[t >> 5] = m1; sm2[t >> 5] = m2; }
    __syncthreads();
    m1 = sm1[0]; m2 = sm2[0];
#pragma unroll
    for (int i = 1; i < 8; ++i) { m1 = fmaxf(m1, sm1[i]); m2 = fmaxf(m2, sm2[i]); }
    float s1 = 0.f, s2 = 0.f;
#pragma unroll
    for (int i = 0; i < 8; ++i) {
        v1[i] = expf(v1[i] - m1); s1 += v1[i];
        v2[i] = expf(v2[i] - m2); s2 += v2[i];
    }
#pragma unroll
    for (int o = 16; o; o >>= 1) {
        s1 += __shfl_xor_sync(0xffffffffu, s1, o);
        s2 += __shfl_xor_sync(0xffffffffu, s2, o);
    }
    __syncthreads();
    if ((t & 31) == 0) { sm1[t >> 5] = s1; sm2[t >> 5] = s2; }
    __syncthreads();
    s1 = 0.f; s2 = 0.f;
#pragma unroll
    for (int i = 0; i < 8; ++i) { s1 += sm1[i]; s2 += sm2[i]; }
    const float i1 = 1.f / s1;
    const float i2 = g_lam[h] / s2;
    float* w = attn + off;
#pragma unroll
    for (int i = 0; i < 8; ++i)
        w[t + (i << 8)] = v1[i] * i1 - v2[i] * i2;
}

// group g = h*2 + (q>=1024): contiguous 262144-float block of g_o
__global__ void group_stats_kernel(const float* __restrict__ ob)
{
    const int g = blockIdx.x;
    const float4* p = (const float4*)(ob + (long long)g * 262144);
    float s = 0.f, ss = 0.f;
    for (int i = threadIdx.x; i < 65536; i += 1024) {
        float4 v = p[i];
        s  += v.x + v.y + v.z + v.w;
        ss += v.x * v.x + v.y * v.y + v.z * v.z + v.w * v.w;
    }
    __shared__ float sa[32], sb[32];
    int t = threadIdx.x;
#pragma unroll
    for (int o = 16; o; o >>= 1) {
        s  += __shfl_xor_sync(0xffffffffu, s, o);
        ss += __shfl_xor_sync(0xffffffffu, ss, o);
    }
    if ((t & 31) == 0) { sa[t >> 5] = s; sb[t >> 5] = ss; }
    __syncthreads();
    if (t < 32) {
        s = sa[t]; ss = sb[t];
#pragma unroll
        for (int o = 16; o; o >>= 1) {
            s  += __shfl_xor_sync(0xffffffffu, s, o);
            ss += __shfl_xor_sync(0xffffffffu, ss, o);
        }
        if (t == 0) {
            float mu  = s * (1.f / 262144.f);
            float var = ss * (1.f / 262144.f) - mu * mu;
            g_mu[g]   = mu;
            g_rstd[g] = rsqrtf(var + EPSV);
        }
    }
}

// y_flat[q, h*256+d] = ((o[h,q,d]-mu)*rstd*gamma[r]+beta[r]) * 0.8,  r=(q%1024)>>3
__global__ void apply_norm_kernel(const float* __restrict__ ob,
                                  const float* __restrict__ gamma,
                                  const float* __restrict__ beta,
                                  float* __restrict__ y)
{
    int idx = blockIdx.x * 256 + threadIdx.x;      // over 16*2048*256 = 8388608
    int d = idx & 255;
    int q = (idx >> 8) & 2047;
    int h = idx >> 19;
    int g = (h << 1) + (q >> 10);
    int r = (q & 1023) >> 3;
    float v = (ob[idx] - g_mu[g]) * g_rstd[g] * gamma[r] + beta[r];
    y[((long long)q << 12) + (h << 8) + d] = v * 0.8f;   // *(1-LAMBDA_INIT)
}

// ---------------------------------------------------------------------------
extern "C" void kernel_launch(void* const* d_in, const int* in_sizes, int n_in,
                              void* d_out, int out_size)
{
    const float* X    = (const float*)d_in[0];
    const float* cs   = (const float*)d_in[1];
    const float* sn   = (const float*)d_in[2];
    const float* Wq   = (const float*)d_in[3];
    const float* bq   = (const float*)d_in[4];
    const float* Wk   = (const float*)d_in[5];
    const float* bk   = (const float*)d_in[6];
    const float* Wqn  = (const float*)d_in[7];
    const float* bqn  = (const float*)d_in[8];
    const float* Wkn  = (const float*)d_in[9];
    const float* bkn  = (const float*)d_in[10];
    const float* Wv   = (const float*)d_in[11];
    const float* bv   = (const float*)d_in[12];
    const float* Wo   = (const float*)d_in[13];
    const float* bo   = (const float*)d_in[14];
    const float* lq1  = (const float*)d_in[15];
    const float* lk1  = (const float*)d_in[16];
    const float* lq2  = (const float*)d_in[17];
    const float* lk2  = (const float*)d_in[18];
    const float* gam  = (const float*)d_in[19];
    const float* bet  = (const float*)d_in[20];

    float *pQ, *pK, *pQN, *pKN, *pV, *pVt, *paw, *pan, *po, *py;
    cudaGetSymbolAddress((void**)&pQ,  g_Q);
    cudaGetSymbolAddress((void**)&pK,  g_K);
    cudaGetSymbolAddress((void**)&pQN, g_QN);
    cudaGetSymbolAddress((void**)&pKN, g_KN);
    cudaGetSymbolAddress((void**)&pV,  g_V);
    cudaGetSymbolAddress((void**)&pVt, g_Vt);
    cudaGetSymbolAddress((void**)&paw, g_aw);
    cudaGetSymbolAddress((void**)&pan, g_an);
    cudaGetSymbolAddress((void**)&po,  g_o);
    cudaGetSymbolAddress((void**)&py,  g_y);

    float* outp  = (float*)d_out;
    float* attnp = ((long long)out_size >= OUT_ELEMS + ATTN_ELEMS)
                       ? (outp + OUT_ELEMS) : paw;

    // 1. projections: C = X @ W^T + b   (tf32 tensor cores)
    tgemm_nt<<<dim3(16,16,1), 256>>>(X, Wq,  bq,  pQ,  2048, 2048, 2048, 2048, 0,0,0,0, 1.f);
    tgemm_nt<<<dim3( 8,16,1), 256>>>(X, Wk,  bk,  pK,  2048, 2048, 2048, 1024, 0,0,0,0, 1.f);
    tgemm_nt<<<dim3(16,16,1), 256>>>(X, Wqn, bqn, pQN, 2048, 2048, 2048, 2048, 0,0,0,0, 1.f);
    tgemm_nt<<<dim3( 8,16,1), 256>>>(X, Wkn, bkn, pKN, 2048, 2048, 2048, 1024, 0,0,0,0, 1.f);
    tgemm_nt<<<dim3(16,16,1), 256>>>(X, Wv,  bv,  pV,  2048, 2048, 2048, 2048, 0,0,0,0, 1.f);

    // 2. V transpose (so PV is NT), RoPE, lambda
    transpose2048<<<dim3(64,64), dim3(32,8)>>>(pV, pVt);
    rope_kernel<<<(S_LEN*16*64)/256, 256>>>(pQ,  cs, sn, 16);
    rope_kernel<<<(S_LEN* 8*64)/256, 256>>>(pK,  cs, sn,  8);
    rope_kernel<<<(S_LEN*16*64)/256, 256>>>(pQN, cs, sn, 16);
    rope_kernel<<<(S_LEN* 8*64)/256, 256>>>(pKN, cs, sn,  8);
    lam_kernel<<<16, 128>>>(lq1, lk1, lq2, lk2);

    // 3. scores: aw/an = scale * Q K^T (GQA: kv head = h>>1 via zshB=1)
    tgemm_nt<<<dim3(16,16,16), 256>>>(pQ,  pK,  nullptr, paw, 128, 2048, 1024, 2048,
                                      128, 128, 1, (long long)S_LEN*S_LEN, ATT_SCALE);
    tgemm_nt<<<dim3(16,16,16), 256>>>(pQN, pKN, nullptr, pan, 128, 2048, 1024, 2048,
                                      128, 128, 1, (long long)S_LEN*S_LEN, ATT_SCALE);

    // 4. attn = softmax(aw) - lam*softmax(an)
    softmax_combine<<<dim3(S_LEN, NH), 256>>>(paw, pan, attnp);

    // 5. out = attn @ Vt^T  (B rows = output dims, k-contig after transpose)
    tgemm_nt<<<dim3(2,16,16), 256>>>(attnp, pVt, nullptr, po, 2048, 2048, 2048, 256,
                                     (long long)S_LEN*S_LEN, (long long)256*2048, 1,
                                     (long long)S_LEN*256, 1.f);

    // 6. group stats + normalize/scatter into y_flat [2048, 4096]
    group_stats_kernel<<<32, 1024>>>(po);
    apply_norm_kernel<<<(16*2048*256)/256, 256>>>(po, gam, bet, py);

    // 7. output = y @ Wo^T + bo
    tgemm_nt<<<dim3(16,16,1), 256>>>(py, Wo, bo, outp, 4096, 4096, 4096, 2048,
                                     0,0,0,0, 1.f);
}

// round 3
// speedup vs baseline: 2.8273x; 1.0198x over previous
#include <cuda_runtime.h>
#include <math.h>
#include <stdint.h>

// ---------------------------------------------------------------------------
// DiffAttention  B=1 S=2048 HID=2048 H=16 KVH=8 HD=128
// tf32 tensor cores + cp.async 3-stage pipelined GEMM
// ---------------------------------------------------------------------------
namespace {
constexpr int S_LEN   = 2048;
constexpr int NH      = 16;
constexpr int NKV     = 8;
constexpr int DH      = 128;
constexpr float ATT_SCALE = 0.08838834764831845f;   // 128^-0.5
constexpr float LAM0      = 0.2f;
constexpr float EPSV      = 1e-5f;
constexpr long long ATTN_ELEMS = (long long)NH * S_LEN * S_LEN;   // 67108864
constexpr long long OUT_ELEMS  = (long long)S_LEN * (NH * DH);    // 4194304

constexpr int PITCH   = 20;                 // smem row pitch (conflict-free)
constexpr int STG_F   = 2 * 128 * PITCH;    // floats per stage (A tile + B tile)
constexpr int NSTAGE  = 3;
constexpr int SMEM_BYTES = NSTAGE * STG_F * 4;   // 61440
}

// scratch (device globals: allocation-free contract)
__device__ float g_Q [S_LEN * NH  * DH];
__device__ float g_K [S_LEN * NKV * DH];
__device__ float g_QN[S_LEN * NH  * DH];
__device__ float g_KN[S_LEN * NKV * DH];
__device__ float g_V [S_LEN * NKV * 2 * DH];
__device__ float g_Vt[S_LEN * NKV * 2 * DH];     // V transposed
__device__ float g_aw[(long long)NH * S_LEN * S_LEN];
__device__ float g_an[(long long)NH * S_LEN * S_LEN];
__device__ float g_o [NH * S_LEN * 2 * DH];
__device__ float g_y [S_LEN * NH * 2 * DH];
__device__ float g_lam[NH];
__device__ float g_mu[2 * NH];
__device__ float g_rstd[2 * NH];

// ---------------------------------------------------------------------------
// helpers
// ---------------------------------------------------------------------------
__device__ __forceinline__ uint32_t to_tf32(float x) {
    uint32_t r;
    asm("cvt.rna.tf32.f32 %0, %1;" : "=r"(r) : "f"(x));
    return r;
}
__device__ __forceinline__ void mma_tf32(float* c, const uint32_t* a, const uint32_t* b) {
    asm volatile(
        "mma.sync.aligned.m16n8k8.row.col.f32.tf32.tf32.f32 "
        "{%0,%1,%2,%3}, {%4,%5,%6,%7}, {%8,%9}, {%0,%1,%2,%3};\n"
        : "+f"(c[0]), "+f"(c[1]), "+f"(c[2]), "+f"(c[3])
        : "r"(a[0]), "r"(a[1]), "r"(a[2]), "r"(a[3]),
          "r"(b[0]), "r"(b[1]));
}
__device__ __forceinline__ void cp_async16(uint32_t saddr, const float* gptr) {
    asm volatile("cp.async.ca.shared.global [%0], [%1], 16;\n"
                 :: "r"(saddr), "l"(gptr));
}

// ---------------------------------------------------------------------------
// Tensor-core GEMM NT:  C[m,n] = alpha * sum_k A[m,k]*B[n,k] + bias[n]
// A: [M,K] k-contig (lda), B: [N,K] k-contig (ldb).
// Batched over blockIdx.z:  A += z*sA,  B += (z>>zshB)*sB,  C += z*sC.
// Block tile 128x128, BK=16, 8 warps (2x4), warp tile 64x32 (4x4 m16n8k8).
// 3-stage cp.async pipeline; tf32 rna conversion at fragment load.
// M, N multiples of 128; K multiple of 16 (and >= 48).
// ---------------------------------------------------------------------------
__global__ void __launch_bounds__(256, 2) tgemm_nt(
    const float* __restrict__ A, const float* __restrict__ B,
    const float* __restrict__ bias, float* __restrict__ C,
    int K, int lda, int ldb, int ldc,
    long long sA, long long sB, int zshB, long long sC, float alpha)
{
    extern __shared__ float sm[];   // [NSTAGE][ A:128x20 | B:128x20 ]

    const int z = blockIdx.z;
    A += (long long)z * sA;
    B += (long long)(z >> zshB) * sB;
    C += (long long)z * sC;
    const int m0 = blockIdx.y << 7, n0 = blockIdx.x << 7;
    const int tid  = threadIdx.x;
    const int wid  = tid >> 5, lane = tid & 31;
    const int wm   = (wid & 1) << 6;        // warp m offset: 0 / 64
    const int wn   = (wid >> 1) << 5;       // warp n offset: 0..96
    const int gid  = lane >> 2, tig = lane & 3;

    // staging: each thread moves 2x16B of A and 2x16B of B per 128x16 tile
    const int srow = tid >> 2;              // 0..63
    const int scol = (tid & 3) << 2;        // 0,4,8,12
    const float* Ag = A + (long long)(m0 + srow) * lda + scol;
    const float* Bg = B + (long long)(n0 + srow) * ldb + scol;
    const long long ldA64 = (long long)64 * lda;
    const long long ldB64 = (long long)64 * ldb;

    const uint32_t smBase = (uint32_t)__cvta_generic_to_shared(sm);
    const uint32_t dA0 = smBase + (srow * PITCH + scol) * 4;
    const uint32_t dA1 = smBase + ((srow + 64) * PITCH + scol) * 4;
    const uint32_t dB0 = dA0 + 128 * PITCH * 4;
    const uint32_t dB1 = dA1 + 128 * PITCH * 4;

    float acc[4][4][4];
#pragma unroll
    for (int i = 0; i < 4; ++i)
#pragma unroll
        for (int j = 0; j < 4; ++j)
#pragma unroll
            for (int v = 0; v < 4; ++v) acc[i][j][v] = 0.f;

    const int T = K >> 4;

    // prologue: stage 0 and 1 in flight
#pragma unroll
    for (int s = 0; s < NSTAGE - 1; ++s) {
        const uint32_t off = (uint32_t)(s * STG_F * 4);
        const float* Ap = Ag + (s << 4);
        const float* Bp = Bg + (s << 4);
        cp_async16(dA0 + off, Ap);
        cp_async16(dA1 + off, Ap + ldA64);
        cp_async16(dB0 + off, Bp);
        cp_async16(dB1 + off, Bp + ldB64);
        asm volatile("cp.async.commit_group;\n" ::);
    }

    int ldS = 0;                 // stage being consumed
    int ldN = NSTAGE - 1;        // stage to fill next
    for (int t = 0; t < T; ++t) {
        asm volatile("cp.async.wait_group %0;\n" :: "n"(NSTAGE - 2));
        __syncthreads();

        // issue next tile (overwrites stage finished last iteration)
        if (t + NSTAGE - 1 < T) {
            const uint32_t off = (uint32_t)(ldN * STG_F * 4);
            const float* Ap = Ag + ((t + NSTAGE - 1) << 4);
            const float* Bp = Bg + ((t + NSTAGE - 1) << 4);
            cp_async16(dA0 + off, Ap);
            cp_async16(dA1 + off, Ap + ldA64);
            cp_async16(dB0 + off, Bp);
            cp_async16(dB1 + off, Bp + ldB64);
        }
        asm volatile("cp.async.commit_group;\n" ::);
        if (++ldN == NSTAGE) ldN = 0;

        const float* Ab = sm + ldS * STG_F;
        const float* Bb = Ab + 128 * PITCH;
#pragma unroll
        for (int kk = 0; kk < 16; kk += 8) {
            uint32_t a[4][4], b[4][2];
#pragma unroll
            for (int mt = 0; mt < 4; ++mt) {
                const int r = wm + (mt << 4) + gid;
                a[mt][0] = to_tf32(Ab[r * PITCH + kk + tig]);
                a[mt][1] = to_tf32(Ab[(r + 8) * PITCH + kk + tig]);
                a[mt][2] = to_tf32(Ab[r * PITCH + kk + tig + 4]);
                a[mt][3] = to_tf32(Ab[(r + 8) * PITCH + kk + tig + 4]);
            }
#pragma unroll
            for (int nt = 0; nt < 4; ++nt) {
                const int c = wn + (nt << 3) + gid;
                b[nt][0] = to_tf32(Bb[c * PITCH + kk + tig]);
                b[nt][1] = to_tf32(Bb[c * PITCH + kk + tig + 4]);
            }
#pragma unroll
            for (int mt = 0; mt < 4; ++mt)
#pragma unroll
                for (int nt = 0; nt < 4; ++nt)
                    mma_tf32(acc[mt][nt], a[mt], b[nt]);
        }
        if (++ldS == NSTAGE) ldS = 0;
    }

    // epilogue: alpha * acc + bias, float2 stores
#pragma unroll
    for (int nt = 0; nt < 4; ++nt) {
        const int c0 = n0 + wn + (nt << 3) + (tig << 1);
        const float b0 = bias ? bias[c0]     : 0.f;
        const float b1 = bias ? bias[c0 + 1] : 0.f;
#pragma unroll
        for (int mt = 0; mt < 4; ++mt) {
            const int r = m0 + wm + (mt << 4) + gid;
            float2 v;
            v.x = acc[mt][nt][0] * alpha + b0;
            v.y = acc[mt][nt][1] * alpha + b1;
            *(float2*)&C[(long long)r * ldc + c0] = v;
            v.x = acc[mt][nt][2] * alpha + b0;
            v.y = acc[mt][nt][3] * alpha + b1;
            *(float2*)&C[(long long)(r + 8) * ldc + c0] = v;
        }
    }
}

// ---------------------------------------------------------------------------
// 2048x2048 transpose (for V -> Vt so PV GEMM is NT)
// ---------------------------------------------------------------------------
__global__ void transpose2048(const float* __restrict__ in, float* __restrict__ out)
{
    __shared__ float tile[32][33];
    int x = blockIdx.x * 32 + threadIdx.x;
    int y = blockIdx.y * 32 + threadIdx.y;
#pragma unroll
    for (int i = 0; i < 32; i += 8)
        tile[threadIdx.y + i][threadIdx.x] = in[(long long)(y + i) * 2048 + x];
    __syncthreads();
    x = blockIdx.y * 32 + threadIdx.x;
    y = blockIdx.x * 32 + threadIdx.y;
#pragma unroll
    for (int i = 0; i < 32; i += 8)
        out[(long long)(y + i) * 2048 + x] = tile[threadIdx.x][threadIdx.y + i];
}

// ---------------------------------------------------------------------------
// RoPE in place on [S, HH, 128]; pair (d, d+64)
// ---------------------------------------------------------------------------
__global__ void rope_kernel(float* __restrict__ Xv,
                            const float* __restrict__ cs,
                            const float* __restrict__ sn, int HH)
{
    int idx = blockIdx.x * 256 + threadIdx.x;
    int total = S_LEN * HH * 64;
    if (idx >= total) return;
    int d = idx & 63;
    int h = (idx >> 6) % HH;
    int s = idx / (HH * 64);
    float c0 = cs[s * DH + d],       s0 = sn[s * DH + d];
    float c1 = cs[s * DH + 64 + d],  s1 = sn[s * DH + 64 + d];
    long long base = ((long long)s * HH + h) * DH;
    float x0 = Xv[base + d], x1 = Xv[base + 64 + d];
    Xv[base + d]      = x0 * c0 - x1 * s0;
    Xv[base + 64 + d] = x1 * c1 + x0 * s1;
}

// lam[h] = exp(dot(lq1,lk1)) - exp(dot(lq2,lk2)) + 0.2
__global__ void lam_kernel(const float* __restrict__ lq1, const float* __restrict__ lk1,
                           const float* __restrict__ lq2, const float* __restrict__ lk2)
{
    int h = blockIdx.x, t = threadIdx.x;
    float a = lq1[h * DH + t] * lk1[h * DH + t];
    float b = lq2[h * DH + t] * lk2[h * DH + t];
#pragma unroll
    for (int o = 16; o; o >>= 1) {
        a += __shfl_xor_sync(0xffffffffu, a, o);
        b += __shfl_xor_sync(0xffffffffu, b, o);
    }
    __shared__ float sa[4], sb[4];
    if ((t & 31) == 0) { sa[t >> 5] = a; sb[t >> 5] = b; }
    __syncthreads();
    if (t == 0) {
        float A = sa[0] + sa[1] + sa[2] + sa[3];
        float B = sb[0] + sb[1] + sb[2] + sb[3];
        g_lam[h] = expf(A) - expf(B) + LAM0;
    }
}

// attn = softmax(aw) - lam[h]*softmax(an); one block per (h,q) row.
__global__ void __launch_bounds__(256) softmax_combine(
    const float* __restrict__ aw, const float* __restrict__ an,
    float* __restrict__ attn)
{
    const int q = blockIdx.x, h = blockIdx.y;
    const long long off = ((long long)h * S_LEN + q) * S_LEN;
    const float* r1 = aw + off;
    const float* r2 = an + off;
    const int t = threadIdx.x;
    float v1[8], v2[8];
    float m1 = -1e30f, m2 = -1e30f;
#pragma unroll
    for (int i = 0; i < 8; ++i) {
        v1[i] = r1[t + (i << 8)];
        v2[i] = r2[t + (i << 8)];
        m1 = fmaxf(m1, v1[i]);
        m2 = fmaxf(m2, v2[i]);
    }
    __shared__ float sm1[8], sm2[8];
#pragma unroll
    for (int o = 16; o; o >>= 1) {
        m1 = fmaxf(m1, __shfl_xor_sync(0xffffffffu, m1, o));
        m2 = fmaxf(m2, __shfl_xor_sync(0xffffffffu, m2, o));
    }
    if ((t & 31) == 0) { sm1[t >> 5] = m1; sm2[t >> 5] = m2; }
    __syncthreads();
    m1 = sm1[0]; m2 = sm2[0];
#pragma unroll
    for (int i = 1; i < 8; ++i) { m1 = fmaxf(m1, sm1[i]); m2 = fmaxf(m2, sm2[i]); }
    float s1 = 0.f, s2 = 0.f;
#pragma unroll
    for (int i = 0; i < 8; ++i) {
        v1[i] = expf(v1[i] - m1); s1 += v1[i];
        v2[i] = expf(v2[i] - m2); s2 += v2[i];
    }
#pragma unroll
    for (int o = 16; o; o >>= 1) {
        s1 += __shfl_xor_sync(0xffffffffu, s1, o);
        s2 += __shfl_xor_sync(0xffffffffu, s2, o);
    }
    __syncthreads();
    if ((t & 31) == 0) { sm1[t >> 5] = s1; sm2[t >> 5] = s2; }
    __syncthreads();
    s1 = 0.f; s2 = 0.f;
#pragma unroll
    for (int i = 0; i < 8; ++i) { s1 += sm1[i]; s2 += sm2[i]; }
    const float i1 = 1.f / s1;
    const float i2 = g_lam[h] / s2;
    float* w = attn + off;
#pragma unroll
    for (int i = 0; i < 8; ++i)
        w[t + (i << 8)] = v1[i] * i1 - v2[i] * i2;
}

// group g = h*2 + (q>=1024): contiguous 262144-float block of g_o
__global__ void group_stats_kernel(const float* __restrict__ ob)
{
    const int g = blockIdx.x;
    const float4* p = (const float4*)(ob + (long long)g * 262144);
    float s = 0.f, ss = 0.f;
    for (int i = threadIdx.x; i < 65536; i += 1024) {
        float4 v = p[i];
        s  += v.x + v.y + v.z + v.w;
        ss += v.x * v.x + v.y * v.y + v.z * v.z + v.w * v.w;
    }
    __shared__ float sa[32], sb[32];
    int t = threadIdx.x;
#pragma unroll
    for (int o = 16; o; o >>= 1) {
        s  += __shfl_xor_sync(0xffffffffu, s, o);
        ss += __shfl_xor_sync(0xffffffffu, ss, o);
    }
    if ((t & 31) == 0) { sa[t >> 5] = s; sb[t >> 5] = ss; }
    __syncthreads();
    if (t < 32) {
        s = sa[t]; ss = sb[t];
#pragma unroll
        for (int o = 16; o; o >>= 1) {
            s  += __shfl_xor_sync(0xffffffffu, s, o);
            ss += __shfl_xor_sync(0xffffffffu, ss, o);
        }
        if (t == 0) {
            float mu  = s * (1.f / 262144.f);
            float var = ss * (1.f / 262144.f) - mu * mu;
            g_mu[g]   = mu;
            g_rstd[g] = rsqrtf(var + EPSV);
        }
    }
}

// y_flat[q, h*256+d] = ((o[h,q,d]-mu)*rstd*gamma[r]+beta[r]) * 0.8,  r=(q%1024)>>3
__global__ void apply_norm_kernel(const float* __restrict__ ob,
                                  const float* __restrict__ gamma,
                                  const float* __restrict__ beta,
                                  float* __restrict__ y)
{
    int idx = blockIdx.x * 256 + threadIdx.x;      // over 16*2048*256 = 8388608
    int d = idx & 255;
    int q = (idx >> 8) & 2047;
    int h = idx >> 19;
    int g = (h << 1) + (q >> 10);
    int r = (q & 1023) >> 3;
    float v = (ob[idx] - g_mu[g]) * g_rstd[g] * gamma[r] + beta[r];
    y[((long long)q << 12) + (h << 8) + d] = v * 0.8f;   // *(1-LAMBDA_INIT)
}

// ---------------------------------------------------------------------------
extern "C" void kernel_launch(void* const* d_in, const int* in_sizes, int n_in,
                              void* d_out, int out_size)
{
    const float* X    = (const float*)d_in[0];
    const float* cs   = (const float*)d_in[1];
    const float* sn   = (const float*)d_in[2];
    const float* Wq   = (const float*)d_in[3];
    const float* bq   = (const float*)d_in[4];
    const float* Wk   = (const float*)d_in[5];
    const float* bk   = (const float*)d_in[6];
    const float* Wqn  = (const float*)d_in[7];
    const float* bqn  = (const float*)d_in[8];
    const float* Wkn  = (const float*)d_in[9];
    const float* bkn  = (const float*)d_in[10];
    const float* Wv   = (const float*)d_in[11];
    const float* bv   = (const float*)d_in[12];
    const float* Wo   = (const float*)d_in[13];
    const float* bo   = (const float*)d_in[14];
    const float* lq1  = (const float*)d_in[15];
    const float* lk1  = (const float*)d_in[16];
    const float* lq2  = (const float*)d_in[17];
    const float* lk2  = (const float*)d_in[18];
    const float* gam  = (const float*)d_in[19];
    const float* bet  = (const float*)d_in[20];

    float *pQ, *pK, *pQN, *pKN, *pV, *pVt, *paw, *pan, *po, *py;
    cudaGetSymbolAddress((void**)&pQ,  g_Q);
    cudaGetSymbolAddress((void**)&pK,  g_K);
    cudaGetSymbolAddress((void**)&pQN, g_QN);
    cudaGetSymbolAddress((void**)&pKN, g_KN);
    cudaGetSymbolAddress((void**)&pV,  g_V);
    cudaGetSymbolAddress((void**)&pVt, g_Vt);
    cudaGetSymbolAddress((void**)&paw, g_aw);
    cudaGetSymbolAddress((void**)&pan, g_an);
    cudaGetSymbolAddress((void**)&po,  g_o);
    cudaGetSymbolAddress((void**)&py,  g_y);

    float* outp  = (float*)d_out;
    float* attnp = ((long long)out_size >= OUT_ELEMS + ATTN_ELEMS)
                       ? (outp + OUT_ELEMS) : paw;

    // dynamic smem opt-in (idempotent; executes immediately under capture)
    cudaFuncSetAttribute(tgemm_nt, cudaFuncAttributeMaxDynamicSharedMemorySize,
                         SMEM_BYTES);

    // 1. projections: C = X @ W^T + b   (tf32 tensor cores)
    tgemm_nt<<<dim3(16,16,1), 256, SMEM_BYTES>>>(X, Wq,  bq,  pQ,  2048, 2048, 2048, 2048, 0,0,0,0, 1.f);
    tgemm_nt<<<dim3( 8,16,1), 256, SMEM_BYTES>>>(X, Wk,  bk,  pK,  2048, 2048, 2048, 1024, 0,0,0,0, 1.f);
    tgemm_nt<<<dim3(16,16,1), 256, SMEM_BYTES>>>(X, Wqn, bqn, pQN, 2048, 2048, 2048, 2048, 0,0,0,0, 1.f);
    tgemm_nt<<<dim3( 8,16,1), 256, SMEM_BYTES>>>(X, Wkn, bkn, pKN, 2048, 2048, 2048, 1024, 0,0,0,0, 1.f);
    tgemm_nt<<<dim3(16,16,1), 256, SMEM_BYTES>>>(X, Wv,  bv,  pV,  2048, 2048, 2048, 2048, 0,0,0,0, 1.f);

    // 2. V transpose (so PV is NT), RoPE, lambda
    transpose2048<<<dim3(64,64), dim3(32,8)>>>(pV, pVt);
    rope_kernel<<<(S_LEN*16*64)/256, 256>>>(pQ,  cs, sn, 16);
    rope_kernel<<<(S_LEN* 8*64)/256, 256>>>(pK,  cs, sn,  8);
    rope_kernel<<<(S_LEN*16*64)/256, 256>>>(pQN, cs, sn, 16);
    rope_kernel<<<(S_LEN* 8*64)/256, 256>>>(pKN, cs, sn,  8);
    lam_kernel<<<16, 128>>>(lq1, lk1, lq2, lk2);

    // 3. scores: aw/an = scale * Q K^T (GQA: kv head = h>>1 via zshB=1)
    tgemm_nt<<<dim3(16,16,16), 256, SMEM_BYTES>>>(pQ,  pK,  nullptr, paw, 128, 2048, 1024, 2048,
                                      128, 128, 1, (long long)S_LEN*S_LEN, ATT_SCALE);
    tgemm_nt<<<dim3(16,16,16), 256, SMEM_BYTES>>>(pQN, pKN, nullptr, pan, 128, 2048, 1024, 2048,
                                      128, 128, 1, (long long)S_LEN*S_LEN, ATT_SCALE);

    // 4. attn = softmax(aw) - lam*softmax(an)
    softmax_combine<<<dim3(S_LEN, NH), 256>>>(paw, pan, attnp);

    // 5. out = attn @ Vt^T
    tgemm_nt<<<dim3(2,16,16), 256, SMEM_BYTES>>>(attnp, pVt, nullptr, po, 2048, 2048, 2048, 256,
                                     (long long)S_LEN*S_LEN, (long long)256*2048, 1,
                                     (long long)S_LEN*256, 1.f);

    // 6. group stats + normalize/scatter into y_flat [2048, 4096]
    group_stats_kernel<<<32, 1024>>>(po);
    apply_norm_kernel<<<(16*2048*256)/256, 256>>>(po, gam, bet, py);

    // 7. output = y @ Wo^T + bo
    tgemm_nt<<<dim3(16,16,1), 256, SMEM_BYTES>>>(py, Wo, bo, outp, 4096, 4096, 4096, 2048,
                                     0,0,0,0, 1.f);
}

// round 4
// speedup vs baseline: 3.5394x; 1.2519x over previous
#include <cuda_runtime.h>
#include <math.h>
#include <stdint.h>

// ---------------------------------------------------------------------------
// DiffAttention  B=1 S=2048 HID=2048 H=16 KVH=8 HD=128
// tf32 tensor cores: ldmatrix + swizzled smem + cp.async 4-stage pipeline,
// pre-rounded tf32 operands (no cvt in GEMM mainloop).
// ---------------------------------------------------------------------------
namespace {
constexpr int S_LEN   = 2048;
constexpr int NH      = 16;
constexpr int NKV     = 8;
constexpr int DH      = 128;
constexpr float ATT_SCALE = 0.08838834764831845f;   // 128^-0.5
constexpr float LAM0      = 0.2f;
constexpr float EPSV      = 1e-5f;
constexpr long long ATTN_ELEMS = (long long)NH * S_LEN * S_LEN;   // 67108864
constexpr long long OUT_ELEMS  = (long long)S_LEN * (NH * DH);    // 4194304

constexpr int TILE_BYTES = 128 * 64;          // one 128x16f tile, swizzled: 8KB
constexpr int STG_BYTES  = 2 * TILE_BYTES;    // A + B per stage: 16KB
constexpr int NSTAGE     = 4;
constexpr int SMEM_BYTES = NSTAGE * STG_BYTES;   // 65536
}

// scratch (device globals: allocation-free contract)
__device__ float g_Q [S_LEN * NH  * DH];
__device__ float g_K [S_LEN * NKV * DH];
__device__ float g_QN[S_LEN * NH  * DH];
__device__ float g_KN[S_LEN * NKV * DH];
__device__ float g_V [S_LEN * NKV * 2 * DH];
__device__ float g_Vt[S_LEN * NKV * 2 * DH];     // V transposed, tf32-rounded
__device__ float g_aw[(long long)NH * S_LEN * S_LEN];
__device__ float g_an[(long long)NH * S_LEN * S_LEN];
__device__ float g_o [NH * S_LEN * 2 * DH];
__device__ float g_y [S_LEN * NH * 2 * DH];
__device__ float g_lam[NH];
__device__ float g_mu[2 * NH];
__device__ float g_rstd[2 * NH];
// tf32-rounded copies of harness inputs
__device__ float g_Xr  [S_LEN * 2048];
__device__ float g_Wqr [NH  * DH * 2048];
__device__ float g_Wkr [NKV * DH * 2048];
__device__ float g_Wqnr[NH  * DH * 2048];
__device__ float g_Wknr[NKV * DH * 2048];
__device__ float g_Wvr [2 * NKV * DH * 2048];
__device__ float g_Wor [NH * DH * 4096];

// ---------------------------------------------------------------------------
// helpers
// ---------------------------------------------------------------------------
__device__ __forceinline__ float rnd_tf32(float x) {
    uint32_t r;
    asm("cvt.rna.tf32.f32 %0, %1;" : "=r"(r) : "f"(x));
    return __uint_as_float(r);
}
__device__ __forceinline__ void mma_tf32(float* c, const uint32_t* a, const uint32_t* b) {
    asm volatile(
        "mma.sync.aligned.m16n8k8.row.col.f32.tf32.tf32.f32 "
        "{%0,%1,%2,%3}, {%4,%5,%6,%7}, {%8,%9}, {%0,%1,%2,%3};\n"
        : "+f"(c[0]), "+f"(c[1]), "+f"(c[2]), "+f"(c[3])
        : "r"(a[0]), "r"(a[1]), "r"(a[2]), "r"(a[3]),
          "r"(b[0]), "r"(b[1]));
}
__device__ __forceinline__ void cp_async16(uint32_t saddr, const float* gptr) {
    asm volatile("cp.async.ca.shared.global [%0], [%1], 16;\n"
                 :: "r"(saddr), "l"(gptr));
}
__device__ __forceinline__ void ldsm4(uint32_t& d0, uint32_t& d1,
                                      uint32_t& d2, uint32_t& d3, uint32_t addr) {
    asm volatile("ldmatrix.sync.aligned.m8n8.x4.shared.b16 {%0,%1,%2,%3}, [%4];"
                 : "=r"(d0), "=r"(d1), "=r"(d2), "=r"(d3) : "r"(addr));
}
// swizzled byte offset inside a 128x16f tile (64B logical rows, 2 per 128B line)
// verified: every ldmatrix 8-row phase hits 8 distinct 16B segments.
__device__ __forceinline__ uint32_t soff(int r, int c) {
    int line = r >> 1;
    int slot = (((r & 1) << 1) | (c >> 3)) ^ (line & 3);
    int h    = ((c >> 2) & 1) ^ (r & 1);
    return (uint32_t)(line * 128 + slot * 32 + h * 16 + (c & 3) * 4);
}

// ---------------------------------------------------------------------------
// Tensor-core GEMM NT:  C[m,n] = alpha * sum_k A[m,k]*B[n,k] + bias[n]
// A: [M,K] k-contig (lda), B: [N,K] k-contig (ldb), both PRE-ROUNDED to tf32.
// Batched over blockIdx.z:  A += z*sA,  B += (z>>zshB)*sB,  C += z*sC.
// Block tile 128x128, BK=16, 8 warps (2x4), warp tile 64x32 (4x4 m16n8k8).
// ldmatrix fragment loads from XOR-swizzled smem, 4-stage cp.async pipeline.
// M, N multiples of 128; K multiple of 16.
// ---------------------------------------------------------------------------
__global__ void __launch_bounds__(256, 2) tgemm_nt(
    const float* __restrict__ A, const float* __restrict__ B,
    const float* __restrict__ bias, float* __restrict__ C,
    int K, int lda, int ldb, int ldc,
    long long sA, long long sB, int zshB, long long sC, float alpha)
{
    extern __shared__ float sm[];

    const int z = blockIdx.z;
    A += (long long)z * sA;
    B += (long long)(z >> zshB) * sB;
    C += (long long)z * sC;
    const int m0 = blockIdx.y << 7, n0 = blockIdx.x << 7;
    const int tid  = threadIdx.x;
    const int wid  = tid >> 5, lane = tid & 31;
    const int wm   = (wid & 1) << 6;        // warp m offset: 0 / 64
    const int wn   = (wid >> 1) << 5;       // warp n offset: 0..96
    const int gid  = lane >> 2, tig = lane & 3;

    // cp.async staging: each thread moves 2x16B of A and 2x16B of B per tile
    const int srow = tid >> 2;              // 0..63
    const int scol = (tid & 3) << 2;        // 0,4,8,12
    const float* Ag = A + (long long)(m0 + srow) * lda + scol;
    const float* Bg = B + (long long)(n0 + srow) * ldb + scol;
    const long long ldA64 = (long long)64 * lda;
    const long long ldB64 = (long long)64 * ldb;

    const uint32_t smBase = (uint32_t)__cvta_generic_to_shared(sm);
    const uint32_t stA0 = soff(srow,      scol);
    const uint32_t stA1 = soff(srow + 64, scol);

    // ldmatrix base offsets (relative, XOR ^32 selects kk=8 half)
    const int sub = lane >> 3, li = lane & 7;
    const uint32_t aRel = soff(wm + ((sub & 1) << 3) + li, (sub >> 1) << 2);
    const uint32_t bRel = soff(wn + ((sub >> 1) << 3) + li, (sub & 1) << 2);

    float acc[4][4][4];
#pragma unroll
    for (int i = 0; i < 4; ++i)
#pragma unroll
        for (int j = 0; j < 4; ++j)
#pragma unroll
            for (int v = 0; v < 4; ++v) acc[i][j][v] = 0.f;

    const int T = K >> 4;

    // prologue: fill stages 0..NSTAGE-2
#pragma unroll
    for (int s = 0; s < NSTAGE - 1; ++s) {
        if (s < T) {
            const uint32_t off = smBase + s * STG_BYTES;
            const float* Ap = Ag + (s << 4);
            const float* Bp = Bg + (s << 4);
            cp_async16(off + stA0, Ap);
            cp_async16(off + stA1, Ap + ldA64);
            cp_async16(off + TILE_BYTES + stA0, Bp);
            cp_async16(off + TILE_BYTES + stA1, Bp + ldB64);
        }
        asm volatile("cp.async.commit_group;\n" ::);
    }

    int ldS = 0;                 // stage being consumed
    int ldN = NSTAGE - 1;        // stage to fill next
    for (int t = 0; t < T; ++t) {
        asm volatile("cp.async.wait_group %0;\n" :: "n"(NSTAGE - 2));
        __syncthreads();

        if (t + NSTAGE - 1 < T) {
            const uint32_t off = smBase + ldN * STG_BYTES;
            const float* Ap = Ag + ((t + NSTAGE - 1) << 4);
            const float* Bp = Bg + ((t + NSTAGE - 1) << 4);
            cp_async16(off + stA0, Ap);
            cp_async16(off + stA1, Ap + ldA64);
            cp_async16(off + TILE_BYTES + stA0, Bp);
            cp_async16(off + TILE_BYTES + stA1, Bp + ldB64);
        }
        asm volatile("cp.async.commit_group;\n" ::);
        if (++ldN == NSTAGE) ldN = 0;

        const uint32_t stOff = smBase + ldS * STG_BYTES;
#pragma unroll
        for (int kh = 0; kh < 2; ++kh) {
            const uint32_t kx = kh ? 32u : 0u;
            uint32_t a[4][4], b[4][2];
#pragma unroll
            for (int mt = 0; mt < 4; ++mt)
                ldsm4(a[mt][0], a[mt][1], a[mt][2], a[mt][3],
                      stOff + mt * 1024 + (aRel ^ kx));
#pragma unroll
            for (int j = 0; j < 2; ++j)
                ldsm4(b[2*j][0], b[2*j][1], b[2*j+1][0], b[2*j+1][1],
                      stOff + TILE_BYTES + j * 1024 + (bRel ^ kx));
#pragma unroll
            for (int mt = 0; mt < 4; ++mt)
#pragma unroll
                for (int nt = 0; nt < 4; ++nt)
                    mma_tf32(acc[mt][nt], a[mt], b[nt]);
        }
        if (++ldS == NSTAGE) ldS = 0;
    }

    // epilogue: alpha * acc + bias, float2 stores
#pragma unroll
    for (int nt = 0; nt < 4; ++nt) {
        const int c0 = n0 + wn + (nt << 3) + (tig << 1);
        const float b0 = bias ? bias[c0]     : 0.f;
        const float b1 = bias ? bias[c0 + 1] : 0.f;
#pragma unroll
        for (int mt = 0; mt < 4; ++mt) {
            const int r = m0 + wm + (mt << 4) + gid;
            float2 v;
            v.x = acc[mt][nt][0] * alpha + b0;
            v.y = acc[mt][nt][1] * alpha + b1;
            *(float2*)&C[(long long)r * ldc + c0] = v;
            v.x = acc[mt][nt][2] * alpha + b0;
            v.y = acc[mt][nt][3] * alpha + b1;
            *(float2*)&C[(long long)(r + 8) * ldc + c0] = v;
        }
    }
}

// ---------------------------------------------------------------------------
// rna-round a tensor to tf32 (float4 vectorized)
// ---------------------------------------------------------------------------
__global__ void round_copy(const float4* __restrict__ in, float4* __restrict__ out, int n4)
{
    int i = blockIdx.x * 256 + threadIdx.x;
    if (i >= n4) return;
    float4 v = in[i];
    v.x = rnd_tf32(v.x); v.y = rnd_tf32(v.y);
    v.z = rnd_tf32(v.z); v.w = rnd_tf32(v.w);
    out[i] = v;
}

// ---------------------------------------------------------------------------
// 2048x2048 transpose, tf32-rounded output (V -> Vt so PV GEMM is NT)
// ---------------------------------------------------------------------------
__global__ void transpose2048(const float* __restrict__ in, float* __restrict__ out)
{
    __shared__ float tile[32][33];
    int x = blockIdx.x * 32 + threadIdx.x;
    int y = blockIdx.y * 32 + threadIdx.y;
#pragma unroll
    for (int i = 0; i < 32; i += 8)
        tile[threadIdx.y + i][threadIdx.x] = in[(long long)(y + i) * 2048 + x];
    __syncthreads();
    x = blockIdx.y * 32 + threadIdx.x;
    y = blockIdx.x * 32 + threadIdx.y;
#pragma unroll
    for (int i = 0; i < 32; i += 8)
        out[(long long)(y + i) * 2048 + x] = rnd_tf32(tile[threadIdx.x][threadIdx.y + i]);
}

// ---------------------------------------------------------------------------
// RoPE in place on [S, HH, 128]; pair (d, d+64); tf32-rounded output
// ---------------------------------------------------------------------------
__global__ void rope_kernel(float* __restrict__ Xv,
                            const float* __restrict__ cs,
                            const float* __restrict__ sn, int HH)
{
    int idx = blockIdx.x * 256 + threadIdx.x;
    int total = S_LEN * HH * 64;
    if (idx >= total) return;
    int d = idx & 63;
    int h = (idx >> 6) % HH;
    int s = idx / (HH * 64);
    float c0 = cs[s * DH + d],       s0 = sn[s * DH + d];
    float c1 = cs[s * DH + 64 + d],  s1 = sn[s * DH + 64 + d];
    long long base = ((long long)s * HH + h) * DH;
    float x0 = Xv[base + d], x1 = Xv[base + 64 + d];
    Xv[base + d]      = rnd_tf32(x0 * c0 - x1 * s0);
    Xv[base + 64 + d] = rnd_tf32(x1 * c1 + x0 * s1);
}

// lam[h] = exp(dot(lq1,lk1)) - exp(dot(lq2,lk2)) + 0.2
__global__ void lam_kernel(const float* __restrict__ lq1, const float* __restrict__ lk1,
                           const float* __restrict__ lq2, const float* __restrict__ lk2)
{
    int h = blockIdx.x, t = threadIdx.x;
    float a = lq1[h * DH + t] * lk1[h * DH + t];
    float b = lq2[h * DH + t] * lk2[h * DH + t];
#pragma unroll
    for (int o = 16; o; o >>= 1) {
        a += __shfl_xor_sync(0xffffffffu, a, o);
        b += __shfl_xor_sync(0xffffffffu, b, o);
    }
    __shared__ float sa[4], sb[4];
    if ((t & 31) == 0) { sa[t >> 5] = a; sb[t >> 5] = b; }
    __syncthreads();
    if (t == 0) {
        float A = sa[0] + sa[1] + sa[2] + sa[3];
        float B = sb[0] + sb[1] + sb[2] + sb[3];
        g_lam[h] = expf(A) - expf(B) + LAM0;
    }
}

// attn = softmax(aw) - lam[h]*softmax(an); tf32-rounded (feeds PV GEMM).
__global__ void __launch_bounds__(256) softmax_combine(
    const float* __restrict__ aw, const float* __restrict__ an,
    float* __restrict__ attn)
{
    const int q = blockIdx.x, h = blockIdx.y;
    const long long off = ((long long)h * S_LEN + q) * S_LEN;
    const float* r1 = aw + off;
    const float* r2 = an + off;
    const int t = threadIdx.x;
    float v1[8], v2[8];
    float m1 = -1e30f, m2 = -1e30f;
#pragma unroll
    for (int i = 0; i < 8; ++i) {
        v1[i] = r1[t + (i << 8)];
        v2[i] = r2[t + (i << 8)];
        m1 = fmaxf(m1, v1[i]);
        m2 = fmaxf(m2, v2[i]);
    }
    __shared__ float sm1[8], sm2[8];
#pragma unroll
    for (int o = 16; o; o >>= 1) {
        m1 = fmaxf(m1, __shfl_xor_sync(0xffffffffu, m1, o));
        m2 = fmaxf(m2, __shfl_xor_sync(0xffffffffu, m2, o));
    }
    if ((t & 31) == 0) { sm1[t >> 5] = m1; sm2[t >> 5] = m2; }
    __syncthreads();
    m1 = sm1[0]; m2 = sm2[0];
#pragma unroll
    for (int i = 1; i < 8; ++i) { m1 = fmaxf(m1, sm1[i]); m2 = fmaxf(m2, sm2[i]); }
    float s1 = 0.f, s2 = 0.f;
#pragma unroll
    for (int i = 0; i < 8; ++i) {
        v1[i] = expf(v1[i] - m1); s1 += v1[i];
        v2[i] = expf(v2[i] - m2); s2 += v2[i];
    }
#pragma unroll
    for (int o = 16; o; o >>= 1) {
        s1 += __shfl_xor_sync(0xffffffffu, s1, o);
        s2 += __shfl_xor_sync(0xffffffffu, s2, o);
    }
    __syncthreads();
    if ((t & 31) == 0) { sm1[t >> 5] = s1; sm2[t >> 5] = s2; }
    __syncthreads();
    s1 = 0.f; s2 = 0.f;
#pragma unroll
    for (int i = 0; i < 8; ++i) { s1 += sm1[i]; s2 += sm2[i]; }
    const float i1 = 1.f / s1;
    const float i2 = g_lam[h] / s2;
    float* w = attn + off;
#pragma unroll
    for (int i = 0; i < 8; ++i)
        w[t + (i << 8)] = rnd_tf32(v1[i] * i1 - v2[i] * i2);
}

// group g = h*2 + (q>=1024): contiguous 262144-float block of g_o
__global__ void group_stats_kernel(const float* __restrict__ ob)
{
    const int g = blockIdx.x;
    const float4* p = (const float4*)(ob + (long long)g * 262144);
    float s = 0.f, ss = 0.f;
    for (int i = threadIdx.x; i < 65536; i += 1024) {
        float4 v = p[i];
        s  += v.x + v.y + v.z + v.w;
        ss += v.x * v.x + v.y * v.y + v.z * v.z + v.w * v.w;
    }
    __shared__ float sa[32], sb[32];
    int t = threadIdx.x;
#pragma unroll
    for (int o = 16; o; o >>= 1) {
        s  += __shfl_xor_sync(0xffffffffu, s, o);
        ss += __shfl_xor_sync(0xffffffffu, ss, o);
    }
    if ((t & 31) == 0) { sa[t >> 5] = s; sb[t >> 5] = ss; }
    __syncthreads();
    if (t < 32) {
        s = sa[t]; ss = sb[t];
#pragma unroll
        for (int o = 16; o; o >>= 1) {
            s  += __shfl_xor_sync(0xffffffffu, s, o);
            ss += __shfl_xor_sync(0xffffffffu, ss, o);
        }
        if (t == 0) {
            float mu  = s * (1.f / 262144.f);
            float var = ss * (1.f / 262144.f) - mu * mu;
            g_mu[g]   = mu;
            g_rstd[g] = rsqrtf(var + EPSV);
        }
    }
}

// y_flat[q, h*256+d] = tf32(((o-mu)*rstd*gamma[r]+beta[r]) * 0.8), r=(q%1024)>>3
__global__ void apply_norm_kernel(const float* __restrict__ ob,
                                  const float* __restrict__ gamma,
                                  const float* __restrict__ beta,
                                  float* __restrict__ y)
{
    int idx = blockIdx.x * 256 + threadIdx.x;      // over 16*2048*256 = 8388608
    int d = idx & 255;
    int q = (idx >> 8) & 2047;
    int h = idx >> 19;
    int g = (h << 1) + (q >> 10);
    int r = (q & 1023) >> 3;
    float v = (ob[idx] - g_mu[g]) * g_rstd[g] * gamma[r] + beta[r];
    y[((long long)q << 12) + (h << 8) + d] = rnd_tf32(v * 0.8f);
}

// ---------------------------------------------------------------------------
extern "C" void kernel_launch(void* const* d_in, const int* in_sizes, int n_in,
                              void* d_out, int out_size)
{
    const float* X    = (const float*)d_in[0];
    const float* cs   = (const float*)d_in[1];
    const float* sn   = (const float*)d_in[2];
    const float* Wq   = (const float*)d_in[3];
    const float* bq   = (const float*)d_in[4];
    const float* Wk   = (const float*)d_in[5];
    const float* bk   = (const float*)d_in[6];
    const float* Wqn  = (const float*)d_in[7];
    const float* bqn  = (const float*)d_in[8];
    const float* Wkn  = (const float*)d_in[9];
    const float* bkn  = (const float*)d_in[10];
    const float* Wv   = (const float*)d_in[11];
    const float* bv   = (const float*)d_in[12];
    const float* Wo   = (const float*)d_in[13];
    const float* bo   = (const float*)d_in[14];
    const float* lq1  = (const float*)d_in[15];
    const float* lk1  = (const float*)d_in[16];
    const float* lq2  = (const float*)d_in[17];
    const float* lk2  = (const float*)d_in[18];
    const float* gam  = (const float*)d_in[19];
    const float* bet  = (const float*)d_in[20];

    float *pQ, *pK, *pQN, *pKN, *pV, *pVt, *paw, *pan, *po, *py;
    float *pXr, *pWqr, *pWkr, *pWqnr, *pWknr, *pWvr, *pWor;
    cudaGetSymbolAddress((void**)&pQ,  g_Q);
    cudaGetSymbolAddress((void**)&pK,  g_K);
    cudaGetSymbolAddress((void**)&pQN, g_QN);
    cudaGetSymbolAddress((void**)&pKN, g_KN);
    cudaGetSymbolAddress((void**)&pV,  g_V);
    cudaGetSymbolAddress((void**)&pVt, g_Vt);
    cudaGetSymbolAddress((void**)&paw, g_aw);
    cudaGetSymbolAddress((void**)&pan, g_an);
    cudaGetSymbolAddress((void**)&po,  g_o);
    cudaGetSymbolAddress((void**)&py,  g_y);
    cudaGetSymbolAddress((void**)&pXr,   g_Xr);
    cudaGetSymbolAddress((void**)&pWqr,  g_Wqr);
    cudaGetSymbolAddress((void**)&pWkr,  g_Wkr);
    cudaGetSymbolAddress((void**)&pWqnr, g_Wqnr);
    cudaGetSymbolAddress((void**)&pWknr, g_Wknr);
    cudaGetSymbolAddress((void**)&pWvr,  g_Wvr);
    cudaGetSymbolAddress((void**)&pWor,  g_Wor);

    float* outp  = (float*)d_out;
    float* attnp = ((long long)out_size >= OUT_ELEMS + ATTN_ELEMS)
                       ? (outp + OUT_ELEMS) : paw;

    cudaFuncSetAttribute(tgemm_nt, cudaFuncAttributeMaxDynamicSharedMemorySize,
                         SMEM_BYTES);

    // 0. tf32 rounding passes over inputs
    round_copy<<< 4096, 256>>>((const float4*)X,   (float4*)pXr,   1048576);
    round_copy<<< 4096, 256>>>((const float4*)Wq,  (float4*)pWqr,  1048576);
    round_copy<<< 2048, 256>>>((const float4*)Wk,  (float4*)pWkr,   524288);
    round_copy<<< 4096, 256>>>((const float4*)Wqn, (float4*)pWqnr, 1048576);
    round_copy<<< 2048, 256>>>((const float4*)Wkn, (float4*)pWknr,  524288);
    round_copy<<< 8192, 256>>>((const float4*)Wv,  (float4*)pWvr,  2097152);
    round_copy<<< 8192, 256>>>((const float4*)Wo,  (float4*)pWor,  2097152);

    // 1. projections: C = X @ W^T + b
    tgemm_nt<<<dim3(16,16,1), 256, SMEM_BYTES>>>(pXr, pWqr,  bq,  pQ,  2048, 2048, 2048, 2048, 0,0,0,0, 1.f);
    tgemm_nt<<<dim3( 8,16,1), 256, SMEM_BYTES>>>(pXr, pWkr,  bk,  pK,  2048, 2048, 2048, 1024, 0,0,0,0, 1.f);
    tgemm_nt<<<dim3(16,16,1), 256, SMEM_BYTES>>>(pXr, pWqnr, bqn, pQN, 2048, 2048, 2048, 2048, 0,0,0,0, 1.f);
    tgemm_nt<<<dim3( 8,16,1), 256, SMEM_BYTES>>>(pXr, pWknr, bkn, pKN, 2048, 2048, 2048, 1024, 0,0,0,0, 1.f);
    tgemm_nt<<<dim3(16,16,1), 256, SMEM_BYTES>>>(pXr, pWvr,  bv,  pV,  2048, 2048, 2048, 2048, 0,0,0,0, 1.f);

    // 2. V transpose (rounded), RoPE (rounded), lambda
    transpose2048<<<dim3(64,64), dim3(32,8)>>>(pV, pVt);
    rope_kernel<<<(S_LEN*16*64)/256, 256>>>(pQ,  cs, sn, 16);
    rope_kernel<<<(S_LEN* 8*64)/256, 256>>>(pK,  cs, sn,  8);
    rope_kernel<<<(S_LEN*16*64)/256, 256>>>(pQN, cs, sn, 16);
    rope_kernel<<<(S_LEN* 8*64)/256, 256>>>(pKN, cs, sn,  8);
    lam_kernel<<<16, 128>>>(lq1, lk1, lq2, lk2);

    // 3. scores: aw/an = scale * Q K^T (GQA: kv head = h>>1 via zshB=1)
    tgemm_nt<<<dim3(16,16,16), 256, SMEM_BYTES>>>(pQ,  pK,  nullptr, paw, 128, 2048, 1024, 2048,
                                      128, 128, 1, (long long)S_LEN*S_LEN, ATT_SCALE);
    tgemm_nt<<<dim3(16,16,16), 256, SMEM_BYTES>>>(pQN, pKN, nullptr, pan, 128, 2048, 1024, 2048,
                                      128, 128, 1, (long long)S_LEN*S_LEN, ATT_SCALE);

    // 4. attn = softmax(aw) - lam*softmax(an)  (tf32-rounded)
    softmax_combine<<<dim3(S_LEN, NH), 256>>>(paw, pan, attnp);

    // 5. out = attn @ Vt^T
    tgemm_nt<<<dim3(2,16,16), 256, SMEM_BYTES>>>(attnp, pVt, nullptr, po, 2048, 2048, 2048, 256,
                                     (long long)S_LEN*S_LEN, (long long)256*2048, 1,
                                     (long long)S_LEN*256, 1.f);

    // 6. group stats + normalize/scatter into y_flat [2048, 4096] (rounded)
    group_stats_kernel<<<32, 1024>>>(po);
    apply_norm_kernel<<<(16*2048*256)/256, 256>>>(po, gam, bet, py);

    // 7. output = y @ Wo^T + bo
    tgemm_nt<<<dim3(16,16,1), 256, SMEM_BYTES>>>(py, pWor, bo, outp, 4096, 4096, 4096, 2048,
                                     0,0,0,0, 1.f);
}